// round 11
// baseline (speedup 1.0000x reference)
#include <cuda_runtime.h>
#include <math.h>

// Problem constants
#define LQ 128     // sequence length
#define TT 127     // T = L-1 output rows
#define EE 256     // embedding dim
#define HH 512     // hidden
#define G4 2048    // 4*H gates
#define VV 32000   // vocab
#define KH2 1024   // 2*H

#define RT 8       // backward rows per tile in step kernel

// ---------------- device scratch (no allocs allowed) ----------------
__device__ float g_gxf[LQ][G4];        // emb @ W_ih_f^T + b_f
__device__ float g_gxb[LQ][G4];        // emb @ W_ih_b^T + b_b
__device__ float g_hf_all[TT][HH];     // forward hidden states hs_f[:127]
__device__ float g_hb_final[TT][HH];   // final backward hidden per row t
__device__ float g_hb[2][TT][HH];      // double-buffered backward h
__device__ float g_cb[2][TT][HH];      // double-buffered backward c
__device__ float g_hfwd[2][HH];        // forward h
__device__ float g_cfwd[2][HH];        // forward c

__device__ __forceinline__ float sigmoidf_(float x) {
    return 1.f / (1.f + expf(-x));
}

// ---------------- init: zero the parity-0 state buffers ----------------
__global__ void init_kernel() {
    int idx = blockIdx.x * blockDim.x + threadIdx.x;
    int stride = gridDim.x * blockDim.x;
    float* hb0 = &g_hb[0][0][0];
    float* cb0 = &g_cb[0][0][0];
    for (int i = idx; i < TT * HH; i += stride) { hb0[i] = 0.f; cb0[i] = 0.f; }
    if (idx < HH) { g_hfwd[0][idx] = 0.f; g_cfwd[0][idx] = 0.f; }
}

// ---------------- gather + input GEMM (both directions) ----------------
// grid: 256 blocks (128 fwd + 128 bwd), each handles 16 gate rows x all 128 t
__global__ void input_gemm_kernel(const int* __restrict__ x,
                                  const float* __restrict__ emb,
                                  const float* __restrict__ Wf,
                                  const float* __restrict__ bif,
                                  const float* __restrict__ bhf,
                                  const float* __restrict__ Wb,
                                  const float* __restrict__ bib,
                                  const float* __restrict__ bhb) {
    __shared__ float sW[16][EE];   // 16KB
    bool isB = (blockIdx.x >= 128);
    int j0 = (isB ? (blockIdx.x - 128) : blockIdx.x) * 16;
    const float* W  = isB ? Wb  : Wf;
    const float* bi = isB ? bib : bif;
    const float* bh = isB ? bhb : bhf;
    int tid = threadIdx.x;  // 128 threads

    for (int u = tid; u < 16 * EE; u += 128)
        sW[u >> 8][u & 255] = W[(j0 + (u >> 8)) * EE + (u & 255)];
    __syncthreads();

    int t = tid;                          // one t per thread
    int tok = x[t];
    const float* er = emb + (long)tok * EE;
    float acc[16];
#pragma unroll
    for (int r = 0; r < 16; r++) acc[r] = 0.f;

    for (int e = 0; e < EE; e += 4) {
        float4 e4 = *(const float4*)(er + e);
#pragma unroll
        for (int r = 0; r < 16; r++) {
            float4 w4 = *(const float4*)&sW[r][e];
            acc[r] += e4.x * w4.x + e4.y * w4.y + e4.z * w4.z + e4.w * w4.w;
        }
    }
    float* gx = isB ? &g_gxb[t][0] : &g_gxf[t][0];
#pragma unroll
    for (int r = 0; r < 16; r++) {
        int j = j0 + r;
        gx[j] = acc[r] + bi[j] + bh[j];
    }
}

// ---------------- one global LSTM step ----------------
// grid.x = 16 k-chunks (32 h-dims x 4 gates each), grid.y = bwd row tiles + 1 fwd tile
// 128 threads: tid>>5 = gate (i,f,g,o), tid&31 = k within chunk
__global__ void step_kernel(int s,
                            const float* __restrict__ Whf,
                            const float* __restrict__ Whb) {
    __shared__ float sh[RT][HH];        // 16KB h tile
    __shared__ float sg[4][RT][32];     // 4KB gate staging
    int tid  = threadIdx.x;
    int gate = tid >> 5;
    int kk   = tid & 31;
    int k0   = blockIdx.x * 32;
    int j    = gate * HH + k0 + kk;
    int p    = s & 1, p2 = p ^ 1;
    bool isFwd = (blockIdx.y == gridDim.y - 1);

    if (isFwd) {
        for (int u = tid; u < HH; u += 128) sh[0][u] = g_hfwd[p][u];
        __syncthreads();
        const float* W = Whf + (long)j * HH;
        float acc = g_gxf[s][j];
        for (int k = 0; k < HH; k += 4) {
            float4 w4 = *(const float4*)(W + k);
            float4 h4 = *(const float4*)&sh[0][k];
            acc += w4.x * h4.x + w4.y * h4.y + w4.z * h4.z + w4.w * h4.w;
        }
        sg[gate][0][kk] = acc;
        __syncthreads();
        if (tid < 32) {
            int k = k0 + tid;
            float iv = sigmoidf_(sg[0][0][tid]);
            float fv = sigmoidf_(sg[1][0][tid]);
            float gv = tanhf(sg[2][0][tid]);
            float ov = sigmoidf_(sg[3][0][tid]);
            float c  = g_cfwd[p][k];
            float cn = fv * c + iv * gv;
            float hn = ov * tanhf(cn);
            g_cfwd[p2][k]   = cn;
            g_hfwd[p2][k]   = hn;
            g_hf_all[s][k]  = hn;   // s in [0,126]
        }
        return;
    }

    // backward tile: rows t0..t0+RT-1, valid while t < TT
    int t0 = s + blockIdx.y * RT;
    for (int u = tid; u < RT * HH; u += 128) {
        int r = u >> 9, k = u & (HH - 1);
        int t = t0 + r;
        sh[r][k] = (t < TT) ? g_hb[p][t][k] : 0.f;
    }
    __syncthreads();

    const float* W = Whb + (long)j * HH;
    float acc[RT];
#pragma unroll
    for (int r = 0; r < RT; r++) acc[r] = 0.f;
    for (int k = 0; k < HH; k += 4) {
        float4 w4 = *(const float4*)(W + k);
#pragma unroll
        for (int r = 0; r < RT; r++) {
            float4 h4 = *(const float4*)&sh[r][k];
            acc[r] += w4.x * h4.x + w4.y * h4.y + w4.z * h4.z + w4.w * h4.w;
        }
    }
#pragma unroll
    for (int r = 0; r < RT; r++) {
        int t = t0 + r;
        if (t < TT) sg[gate][r][kk] = acc[r] + g_gxb[t - s][j];
    }
    __syncthreads();

    // pointwise LSTM update for this block's k-chunk (all 4 gates are local)
    for (int u = tid; u < RT * 32; u += 128) {
        int r = u >> 5, q = u & 31;
        int t = t0 + r;
        if (t >= TT) continue;
        int k = k0 + q;
        float iv = sigmoidf_(sg[0][r][q]);
        float fv = sigmoidf_(sg[1][r][q]);
        float gv = tanhf(sg[2][r][q]);
        float ov = sigmoidf_(sg[3][r][q]);
        float c  = g_cb[p][t][k];
        float cn = fv * c + iv * gv;
        float hn = ov * tanhf(cn);
        g_cb[p2][t][k] = cn;
        g_hb[p2][t][k] = hn;
        if (t == s) g_hb_final[t][k] = hn;   // row t's last active step
    }
}

// ---------------- final FC: logits = [hf|hb] @ fc_w^T + fc_b ----------------
// CTA tile: 32 t x 128 v, K chunked by 32. 256 threads, 4x4 micro-tile each.
#define FCKT 32
__global__ void fc_kernel(const float* __restrict__ fcw,
                          const float* __restrict__ fcb,
                          float* __restrict__ out) {
    __shared__ float As[32][FCKT + 1];    // [t][k], stride 33
    __shared__ float Bs[128][FCKT + 1];   // [v][k], stride 33 (conflict-free reads)
    int tid = threadIdx.x;  // 256
    int i   = tid >> 5;     // 0..7 -> t-sub base 4*i
    int jl  = tid & 31;     // 0..31 -> v lanes (strided by 32)
    int tbase = blockIdx.y * 32;
    int vbase = blockIdx.x * 128;

    float acc[4][4];
#pragma unroll
    for (int a = 0; a < 4; a++)
#pragma unroll
        for (int b = 0; b < 4; b++) acc[a][b] = 0.f;

    for (int kc = 0; kc < KH2; kc += FCKT) {
        for (int u = tid; u < 32 * FCKT; u += 256) {
            int tt = u >> 5, kk = u & 31;
            int t = tbase + tt;
            int k = kc + kk;
            float v = 0.f;
            if (t < TT) v = (k < HH) ? g_hf_all[t][k] : g_hb_final[t][k - HH];
            As[tt][kk] = v;
        }
        for (int u = tid; u < 128 * FCKT; u += 256) {
            int vv = u >> 5, kk = u & 31;
            Bs[vv][kk] = fcw[(long)(vbase + vv) * KH2 + kc + kk];
        }
        __syncthreads();
#pragma unroll
        for (int k = 0; k < FCKT; k++) {
            float av[4], bv[4];
#pragma unroll
            for (int r = 0; r < 4; r++) av[r] = As[4 * i + r][k];
#pragma unroll
            for (int c = 0; c < 4; c++) bv[c] = Bs[jl + 32 * c][k];
#pragma unroll
            for (int r = 0; r < 4; r++)
#pragma unroll
                for (int c = 0; c < 4; c++) acc[r][c] += av[r] * bv[c];
        }
        __syncthreads();
    }
#pragma unroll
    for (int r = 0; r < 4; r++) {
        int t = tbase + 4 * i + r;
        if (t >= TT) continue;
#pragma unroll
        for (int c = 0; c < 4; c++) {
            int v = vbase + jl + 32 * c;
            out[(long)t * VV + v] = acc[r][c] + fcb[v];
        }
    }
}

// ---------------- launch ----------------
extern "C" void kernel_launch(void* const* d_in, const int* in_sizes, int n_in,
                              void* d_out, int out_size) {
    const int*   x      = (const int*)d_in[0];
    const float* emb    = (const float*)d_in[1];
    const float* W_ih_f = (const float*)d_in[2];
    const float* W_hh_f = (const float*)d_in[3];
    const float* b_ih_f = (const float*)d_in[4];
    const float* b_hh_f = (const float*)d_in[5];
    const float* W_ih_b = (const float*)d_in[6];
    const float* W_hh_b = (const float*)d_in[7];
    const float* b_ih_b = (const float*)d_in[8];
    const float* b_hh_b = (const float*)d_in[9];
    const float* fc_w   = (const float*)d_in[10];
    const float* fc_b   = (const float*)d_in[11];
    float* out = (float*)d_out;

    init_kernel<<<64, 256>>>();
    input_gemm_kernel<<<256, 128>>>(x, emb, W_ih_f, b_ih_f, b_hh_f,
                                    W_ih_b, b_ih_b, b_hh_b);
    for (int s = 0; s < TT; s++) {
        int nb = (TT - s + RT - 1) / RT;   // backward row tiles
        dim3 g(16, nb + 1);                // +1 forward tile
        step_kernel<<<g, 128>>>(s, W_hh_f, W_hh_b);
    }
    fc_kernel<<<dim3(VV / 128, 4), 256>>>(fc_w, fc_b, out);
}

// round 12
// speedup vs baseline: 2.0243x; 2.0243x over previous
#include <cuda_runtime.h>
#include <math.h>

// Problem constants
#define LQ 128     // sequence length
#define TT 127     // T = L-1 output rows
#define EE 256     // embedding dim
#define HH 512     // hidden
#define G4 2048    // 4*H gates
#define VV 32000   // vocab
#define KH2 1024   // 2*H

#define NB 128     // persistent scan blocks (one per SM, all co-resident)
#define NT 256     // threads per scan block
#define SW 516     // padded W_b row stride in floats (bank-shift 4/row)
#define TTILE 32   // backward t rows per smem tile

// ---------------- device scratch (no allocs allowed) ----------------
__device__ float g_gxf[LQ][G4];        // emb @ W_ih_f^T + b_f
__device__ float g_gxb[LQ][G4];        // emb @ W_ih_b^T + b_b
__device__ float g_hf_all[TT][HH];     // forward hidden states
__device__ float g_hb_final[TT][HH];   // final backward hidden per row t
__device__ float g_hb[2][TT][HH];      // double-buffered backward h
__device__ float g_hfwd[2][HH];        // double-buffered forward h
__device__ unsigned g_cnt;             // grid barrier arrive counter
__device__ unsigned g_gen;             // grid barrier generation

__device__ __forceinline__ float sigmoidf_(float x) {
    return 1.f / (1.f + expf(-x));
}

// ---------------- init: zero state + barrier vars ----------------
__global__ void init_kernel() {
    int idx = blockIdx.x * blockDim.x + threadIdx.x;
    int stride = gridDim.x * blockDim.x;
    float* hb0 = &g_hb[0][0][0];
    for (int i = idx; i < TT * HH; i += stride) hb0[i] = 0.f;
    if (idx < HH) g_hfwd[0][idx] = 0.f;
    if (idx == 0) { g_cnt = 0u; g_gen = 0u; }
}

// ---------------- gather + input GEMM (both directions) ----------------
__global__ void input_gemm_kernel(const int* __restrict__ x,
                                  const float* __restrict__ emb,
                                  const float* __restrict__ Wf,
                                  const float* __restrict__ bif,
                                  const float* __restrict__ bhf,
                                  const float* __restrict__ Wb,
                                  const float* __restrict__ bib,
                                  const float* __restrict__ bhb) {
    __shared__ float sW[16][EE];
    bool isB = (blockIdx.x >= 128);
    int j0 = (isB ? (blockIdx.x - 128) : blockIdx.x) * 16;
    const float* W  = isB ? Wb  : Wf;
    const float* bi = isB ? bib : bif;
    const float* bh = isB ? bhb : bhf;
    int tid = threadIdx.x;  // 128 threads

    for (int u = tid; u < 16 * EE; u += 128)
        sW[u >> 8][u & 255] = W[(j0 + (u >> 8)) * EE + (u & 255)];
    __syncthreads();

    int t = tid;
    int tok = x[t];
    const float* er = emb + (long)tok * EE;
    float acc[16];
#pragma unroll
    for (int r = 0; r < 16; r++) acc[r] = 0.f;

    for (int e = 0; e < EE; e += 4) {
        float4 e4 = *(const float4*)(er + e);
#pragma unroll
        for (int r = 0; r < 16; r++) {
            float4 w4 = *(const float4*)&sW[r][e];
            acc[r] += e4.x * w4.x + e4.y * w4.y + e4.z * w4.z + e4.w * w4.w;
        }
    }
    float* gx = isB ? &g_gxb[t][0] : &g_gxf[t][0];
#pragma unroll
    for (int r = 0; r < 16; r++) {
        int j = j0 + r;
        gx[j] = acc[r] + bi[j] + bh[j];
    }
}

// ---------------- persistent LSTM scan kernel ----------------
// 128 blocks, each owns hidden dims [4b, 4b+4) => 16 gate rows per direction.
// W slices live in smem for the whole kernel. One grid barrier per step.
extern __shared__ float dyn_smem[];

__global__ void __launch_bounds__(NT, 1)
scan_kernel(const float* __restrict__ Whf, const float* __restrict__ Whb) {
    float* sWb = dyn_smem;               // [16][SW]   33,024 B
    float* sWf = sWb + 16 * SW;          // [16][HH]   32,768 B
    float* sh  = sWf + 16 * HH;          // [TTILE][HH] 65,536 B
    __shared__ float sg[4][TTILE][4];    // gate staging [gate][tt][q]
    __shared__ float scb[TT][4];         // backward c, block's 4 dims
    __shared__ float shf[HH];            // forward h
    __shared__ float sgf[16];            // forward gate staging
    __shared__ float scf[4];             // forward c

    int tid = threadIdx.x;
    int k0 = blockIdx.x * 4;

    // load W slices once (row r = gate*4 + q  ->  global j = gate*HH + k0 + q)
    for (int u = tid; u < 16 * HH; u += NT) {
        int r = u >> 9, k = u & (HH - 1);
        int j = (r >> 2) * HH + k0 + (r & 3);
        sWb[r * SW + k] = Whb[(long)j * HH + k];
        sWf[r * HH + k] = Whf[(long)j * HH + k];
    }
    for (int u = tid; u < TT; u += NT) {
        scb[u][0] = 0.f; scb[u][1] = 0.f; scb[u][2] = 0.f; scb[u][3] = 0.f;
    }
    if (tid < 4) scf[tid] = 0.f;
    __syncthreads();

    int lane = tid & 31;
    int warp = tid >> 5;     // 0..7 = t-group
    int rg   = lane & 3;     // row group (== gate)
    int ksid = lane >> 2;    // 0..7 k split
    int kf   = 4 * ksid;     // k base (floats), strided by 32 per m

    for (int s = 0; s < TT; s++) {
        int p = s & 1, p2 = p ^ 1;

        // ======== forward chain (16 rows) ========
        for (int u = tid; u < HH; u += NT) shf[u] = g_hfwd[p][u];
        __syncthreads();
        {
            int r0 = 2 * warp;   // warp handles rows r0, r0+1
            float a0 = 0.f, a1 = 0.f;
            const float* w0 = sWf + r0 * HH;
            const float* w1 = w0 + HH;
#pragma unroll
            for (int m = 0; m < 16; m++) {
                float h = shf[lane + 32 * m];
                a0 += w0[lane + 32 * m] * h;
                a1 += w1[lane + 32 * m] * h;
            }
#pragma unroll
            for (int off = 16; off >= 1; off >>= 1) {
                a0 += __shfl_xor_sync(0xffffffffu, a0, off);
                a1 += __shfl_xor_sync(0xffffffffu, a1, off);
            }
            if (lane == 0) { sgf[r0] = a0; sgf[r0 + 1] = a1; }
        }
        __syncthreads();
        if (tid < 4) {
            int q = tid, jb = k0 + q;
            float gi = sgf[0 * 4 + q] + g_gxf[s][jb];
            float gf = sgf[1 * 4 + q] + g_gxf[s][HH + jb];
            float gg = sgf[2 * 4 + q] + g_gxf[s][2 * HH + jb];
            float go = sgf[3 * 4 + q] + g_gxf[s][3 * HH + jb];
            float c  = scf[q];
            float cn = sigmoidf_(gf) * c + sigmoidf_(gi) * tanhf(gg);
            float hn = sigmoidf_(go) * tanhf(cn);
            scf[q] = cn;
            g_hfwd[p2][jb]  = hn;
            g_hf_all[s][jb] = hn;
        }

        // ======== backward prefix LSTMs: rows t in [s, 126] ========
        for (int t0 = s; t0 < TT; t0 += TTILE) {
            __syncthreads();
            // stage h tile
            {
                float4 z = make_float4(0.f, 0.f, 0.f, 0.f);
                float4* shd = (float4*)sh;
                for (int u = tid; u < TTILE * (HH / 4); u += NT) {
                    int tt = u >> 7;
                    int t = t0 + tt;
                    shd[u] = (t < TT) ? ((const float4*)&g_hb[p][t][0])[u & 127] : z;
                }
            }
            __syncthreads();

            // micro-tile: 4 rows x 4 t, k-range 64 (stride-32 quads)
            float acc[4][4];
#pragma unroll
            for (int r = 0; r < 4; r++)
#pragma unroll
                for (int i = 0; i < 4; i++) acc[r][i] = 0.f;

            const float* wb0 = sWb + (4 * rg) * SW + kf;
            const float* hp0 = sh + (4 * warp) * HH + kf;
#pragma unroll
            for (int m = 0; m < 16; m++) {
                int o = 32 * m;
                float4 w0 = *(const float4*)(wb0 + o);
                float4 w1 = *(const float4*)(wb0 + SW + o);
                float4 w2 = *(const float4*)(wb0 + 2 * SW + o);
                float4 w3 = *(const float4*)(wb0 + 3 * SW + o);
                float4 h0 = *(const float4*)(hp0 + o);
                float4 h1 = *(const float4*)(hp0 + HH + o);
                float4 h2 = *(const float4*)(hp0 + 2 * HH + o);
                float4 h3 = *(const float4*)(hp0 + 3 * HH + o);
#define DOT4(R,I,W,H) acc[R][I] += W.x*H.x + W.y*H.y + W.z*H.z + W.w*H.w;
                DOT4(0,0,w0,h0) DOT4(0,1,w0,h1) DOT4(0,2,w0,h2) DOT4(0,3,w0,h3)
                DOT4(1,0,w1,h0) DOT4(1,1,w1,h1) DOT4(1,2,w1,h2) DOT4(1,3,w1,h3)
                DOT4(2,0,w2,h0) DOT4(2,1,w2,h1) DOT4(2,2,w2,h2) DOT4(2,3,w2,h3)
                DOT4(3,0,w3,h0) DOT4(3,1,w3,h1) DOT4(3,2,w3,h2) DOT4(3,3,w3,h3)
#undef DOT4
            }

            // reduce over k-split (lane bits 2..4) and stage
#pragma unroll
            for (int r = 0; r < 4; r++)
#pragma unroll
                for (int i = 0; i < 4; i++) {
                    float v = acc[r][i];
                    v += __shfl_xor_sync(0xffffffffu, v, 4);
                    v += __shfl_xor_sync(0xffffffffu, v, 8);
                    v += __shfl_xor_sync(0xffffffffu, v, 16);
                    if (ksid == 0) sg[rg][4 * warp + i][r] = v;
                }
            __syncthreads();

            // pointwise LSTM update for this tile (block's 4 hidden dims)
            int tcnt = TT - t0; if (tcnt > TTILE) tcnt = TTILE;
            for (int it = tid; it < 4 * tcnt; it += NT) {
                int tt = it >> 2, q = it & 3;
                int t = t0 + tt;
                int u = t - s;
                int jb = k0 + q;
                float gi = sg[0][tt][q] + g_gxb[u][jb];
                float gf = sg[1][tt][q] + g_gxb[u][HH + jb];
                float gg = sg[2][tt][q] + g_gxb[u][2 * HH + jb];
                float go = sg[3][tt][q] + g_gxb[u][3 * HH + jb];
                float c  = scb[t][q];
                float cn = sigmoidf_(gf) * c + sigmoidf_(gi) * tanhf(gg);
                float hn = sigmoidf_(go) * tanhf(cn);
                scb[t][q] = cn;
                g_hb[p2][t][jb] = hn;
                if (t == s) g_hb_final[t][jb] = hn;
            }
            __syncthreads();
        }

        // ======== grid barrier ========
        if (tid == 0) {
            __threadfence();
            unsigned a = atomicAdd(&g_cnt, 1u);
            if (a == NB - 1) {
                atomicExch(&g_cnt, 0u);
                __threadfence();
                atomicAdd(&g_gen, 1u);
            } else {
                while (atomicAdd(&g_gen, 0u) < (unsigned)(s + 1)) __nanosleep(64);
            }
            __threadfence();
        }
        __syncthreads();
    }
}

// ---------------- final FC: logits = [hf|hb] @ fc_w^T + fc_b ----------------
#define FCKT 32
__global__ void fc_kernel(const float* __restrict__ fcw,
                          const float* __restrict__ fcb,
                          float* __restrict__ out) {
    __shared__ float As[32][FCKT + 1];
    __shared__ float Bs[128][FCKT + 1];
    int tid = threadIdx.x;  // 256
    int i   = tid >> 5;
    int jl  = tid & 31;
    int tbase = blockIdx.y * 32;
    int vbase = blockIdx.x * 128;

    float acc[4][4];
#pragma unroll
    for (int a = 0; a < 4; a++)
#pragma unroll
        for (int b = 0; b < 4; b++) acc[a][b] = 0.f;

    for (int kc = 0; kc < KH2; kc += FCKT) {
        for (int u = tid; u < 32 * FCKT; u += 256) {
            int tt = u >> 5, kk = u & 31;
            int t = tbase + tt;
            int k = kc + kk;
            float v = 0.f;
            if (t < TT) v = (k < HH) ? g_hf_all[t][k] : g_hb_final[t][k - HH];
            As[tt][kk] = v;
        }
        for (int u = tid; u < 128 * FCKT; u += 256) {
            int vv = u >> 5, kk = u & 31;
            Bs[vv][kk] = fcw[(long)(vbase + vv) * KH2 + kc + kk];
        }
        __syncthreads();
#pragma unroll
        for (int k = 0; k < FCKT; k++) {
            float av[4], bv[4];
#pragma unroll
            for (int r = 0; r < 4; r++) av[r] = As[4 * i + r][k];
#pragma unroll
            for (int c = 0; c < 4; c++) bv[c] = Bs[jl + 32 * c][k];
#pragma unroll
            for (int r = 0; r < 4; r++)
#pragma unroll
                for (int c = 0; c < 4; c++) acc[r][c] += av[r] * bv[c];
        }
        __syncthreads();
    }
#pragma unroll
    for (int r = 0; r < 4; r++) {
        int t = tbase + 4 * i + r;
        if (t >= TT) continue;
#pragma unroll
        for (int c = 0; c < 4; c++) {
            int v = vbase + jl + 32 * c;
            out[(long)t * VV + v] = acc[r][c] + fcb[v];
        }
    }
}

// ---------------- launch ----------------
extern "C" void kernel_launch(void* const* d_in, const int* in_sizes, int n_in,
                              void* d_out, int out_size) {
    const int*   x      = (const int*)d_in[0];
    const float* emb    = (const float*)d_in[1];
    const float* W_ih_f = (const float*)d_in[2];
    const float* W_hh_f = (const float*)d_in[3];
    const float* b_ih_f = (const float*)d_in[4];
    const float* b_hh_f = (const float*)d_in[5];
    const float* W_ih_b = (const float*)d_in[6];
    const float* W_hh_b = (const float*)d_in[7];
    const float* b_ih_b = (const float*)d_in[8];
    const float* b_hh_b = (const float*)d_in[9];
    const float* fc_w   = (const float*)d_in[10];
    const float* fc_b   = (const float*)d_in[11];
    float* out = (float*)d_out;

    const int dynBytes = (16 * SW + 16 * HH + TTILE * HH) * (int)sizeof(float);
    cudaFuncSetAttribute(scan_kernel,
                         cudaFuncAttributeMaxDynamicSharedMemorySize, dynBytes);

    init_kernel<<<64, 256>>>();
    input_gemm_kernel<<<256, 128>>>(x, emb, W_ih_f, b_ih_f, b_hh_f,
                                    W_ih_b, b_ih_b, b_hh_b);
    scan_kernel<<<NB, NT, dynBytes>>>(W_hh_f, W_hh_b);
    fc_kernel<<<dim3(VV / 128, 4), 256>>>(fc_w, fc_b, out);
}

// round 13
// speedup vs baseline: 2.2252x; 1.0993x over previous
#include <cuda_runtime.h>
#include <math.h>

// Problem constants
#define LQ 128     // sequence length
#define TT 127     // T = L-1 output rows
#define EE 256     // embedding dim
#define HH 512     // hidden
#define G4 2048    // 4*H gates
#define VV 32000   // vocab
#define KH2 1024   // 2*H

#define NB 128     // persistent scan blocks (one per SM, all co-resident)
#define NT 256     // threads per scan block
#define TTILE 32   // backward t rows per smem tile

// ---------------- device scratch (no allocs allowed) ----------------
__device__ float g_gxf[LQ][G4];        // emb @ W_ih_f^T + b_f
__device__ float g_gxb[LQ][G4];        // emb @ W_ih_b^T + b_b
__device__ float g_hf_all[TT][HH];     // forward hidden states
__device__ float g_hb_final[TT][HH];   // final backward hidden per row t
__device__ float g_hb[2][TT][HH];      // double-buffered backward h
__device__ float g_hfwd[2][HH];        // double-buffered forward h
__device__ unsigned g_cnt;             // grid barrier arrive counter
__device__ volatile unsigned g_gen;    // grid barrier generation (release flag)

__device__ __forceinline__ float sigmoidf_(float x) {
    return 1.f / (1.f + expf(-x));
}

__device__ __forceinline__ unsigned long long fma2_(unsigned long long a,
                                                    unsigned long long b,
                                                    unsigned long long c) {
    unsigned long long d;
    asm("fma.rn.f32x2 %0, %1, %2, %3;" : "=l"(d) : "l"(a), "l"(b), "l"(c));
    return d;
}

__device__ __forceinline__ float unpack_sum_(unsigned long long p) {
    float lo = __uint_as_float((unsigned)(p & 0xffffffffull));
    float hi = __uint_as_float((unsigned)(p >> 32));
    return lo + hi;
}

// ---------------- init: zero state + barrier vars ----------------
__global__ void init_kernel() {
    int idx = blockIdx.x * blockDim.x + threadIdx.x;
    int stride = gridDim.x * blockDim.x;
    float* hb0 = &g_hb[0][0][0];
    for (int i = idx; i < TT * HH; i += stride) hb0[i] = 0.f;
    if (idx < HH) g_hfwd[0][idx] = 0.f;
    if (idx == 0) { g_cnt = 0u; g_gen = 0u; }
}

// ---------------- gather + input GEMM (both directions) ----------------
__global__ void input_gemm_kernel(const int* __restrict__ x,
                                  const float* __restrict__ emb,
                                  const float* __restrict__ Wf,
                                  const float* __restrict__ bif,
                                  const float* __restrict__ bhf,
                                  const float* __restrict__ Wb,
                                  const float* __restrict__ bib,
                                  const float* __restrict__ bhb) {
    __shared__ float sW[16][EE];
    bool isB = (blockIdx.x >= 128);
    int j0 = (isB ? (blockIdx.x - 128) : blockIdx.x) * 16;
    const float* W  = isB ? Wb  : Wf;
    const float* bi = isB ? bib : bif;
    const float* bh = isB ? bhb : bhf;
    int tid = threadIdx.x;  // 128 threads

    for (int u = tid; u < 16 * EE; u += 128)
        sW[u >> 8][u & 255] = W[(j0 + (u >> 8)) * EE + (u & 255)];
    __syncthreads();

    int t = tid;
    int tok = x[t];
    const float* er = emb + (long)tok * EE;
    float acc[16];
#pragma unroll
    for (int r = 0; r < 16; r++) acc[r] = 0.f;

    for (int e = 0; e < EE; e += 4) {
        float4 e4 = *(const float4*)(er + e);
#pragma unroll
        for (int r = 0; r < 16; r++) {
            float4 w4 = *(const float4*)&sW[r][e];
            acc[r] += e4.x * w4.x + e4.y * w4.y + e4.z * w4.z + e4.w * w4.w;
        }
    }
    float* gx = isB ? &g_gxb[t][0] : &g_gxf[t][0];
#pragma unroll
    for (int r = 0; r < 16; r++) {
        int j = j0 + r;
        gx[j] = acc[r] + bi[j] + bh[j];
    }
}

// ---------------- persistent LSTM scan kernel ----------------
// 128 blocks, each owns hidden dims [4b, 4b+4) => 16 gate rows per direction.
// W slices live in smem for the whole kernel. One grid barrier per step.
// Inner GEMM: micro-tile 4 rows x 8 t, fma.rn.f32x2 packed over k-pairs,
// 16-way k-split reduced via shfl.
extern __shared__ float dyn_smem[];

__global__ void __launch_bounds__(NT, 1)
scan_kernel(const float* __restrict__ Whf, const float* __restrict__ Whb) {
    float* sWb = dyn_smem;               // [16][HH]    32 KB
    float* sWf = sWb + 16 * HH;          // [16][HH]    32 KB
    float* sh  = sWf + 16 * HH;          // [TTILE][HH] 64 KB
    __shared__ float sg[4][TTILE][4];    // gate staging [gate][tt][q]
    __shared__ float scb[TT][4];         // backward c, block's 4 dims
    __shared__ float shf[HH];            // forward h
    __shared__ float sgf[16];            // forward gate staging
    __shared__ float scf[4];             // forward c

    int tid = threadIdx.x;
    int k0 = blockIdx.x * 4;

    // load W slices once (row r = gate*4 + q  ->  global j = gate*HH + k0 + q)
    for (int u = tid; u < 16 * HH; u += NT) {
        int r = u >> 9, k = u & (HH - 1);
        int j = (r >> 2) * HH + k0 + (r & 3);
        sWb[r * HH + k] = Whb[(long)j * HH + k];
        sWf[r * HH + k] = Whf[(long)j * HH + k];
    }
    for (int u = tid; u < TT; u += NT) {
        scb[u][0] = 0.f; scb[u][1] = 0.f; scb[u][2] = 0.f; scb[u][3] = 0.f;
    }
    if (tid < 4) scf[tid] = 0.f;
    __syncthreads();

    int lane = tid & 31;
    int warp = tid >> 5;     // 8 warps
    int rg   = warp & 3;     // row group == gate (rows rg*4 .. rg*4+3)
    int tgh  = warp >> 2;    // 0..1
    int ks   = lane & 15;    // 16-way k-split (k-pairs, strided)
    int tg2  = lane >> 4;    // 0..1
    int tg   = tgh * 2 + tg2;  // 0..3 -> t rows tg*8 .. tg*8+7

    for (int s = 0; s < TT; s++) {
        int p = s & 1, p2 = p ^ 1;

        // ======== forward chain (16 rows) ========
        for (int u = tid; u < HH; u += NT) shf[u] = g_hfwd[p][u];
        __syncthreads();
        {
            int r0 = 2 * warp;   // warp handles rows r0, r0+1
            float a0 = 0.f, a1 = 0.f;
            const float* w0 = sWf + r0 * HH;
            const float* w1 = w0 + HH;
#pragma unroll
            for (int m = 0; m < 16; m++) {
                float h = shf[lane + 32 * m];
                a0 += w0[lane + 32 * m] * h;
                a1 += w1[lane + 32 * m] * h;
            }
#pragma unroll
            for (int off = 16; off >= 1; off >>= 1) {
                a0 += __shfl_xor_sync(0xffffffffu, a0, off);
                a1 += __shfl_xor_sync(0xffffffffu, a1, off);
            }
            if (lane == 0) { sgf[r0] = a0; sgf[r0 + 1] = a1; }
        }
        __syncthreads();
        if (tid < 4) {
            int q = tid, jb = k0 + q;
            float gi = sgf[0 * 4 + q] + g_gxf[s][jb];
            float gf = sgf[1 * 4 + q] + g_gxf[s][HH + jb];
            float gg = sgf[2 * 4 + q] + g_gxf[s][2 * HH + jb];
            float go = sgf[3 * 4 + q] + g_gxf[s][3 * HH + jb];
            float c  = scf[q];
            float cn = sigmoidf_(gf) * c + sigmoidf_(gi) * tanhf(gg);
            float hn = sigmoidf_(go) * tanhf(cn);
            scf[q] = cn;
            g_hfwd[p2][jb]  = hn;
            g_hf_all[s][jb] = hn;
        }

        // ======== backward prefix LSTMs: rows t in [s, 126] ========
        for (int t0 = s; t0 < TT; t0 += TTILE) {
            __syncthreads();
            // stage h tile
            {
                float4 z = make_float4(0.f, 0.f, 0.f, 0.f);
                float4* shd = (float4*)sh;
                for (int u = tid; u < TTILE * (HH / 4); u += NT) {
                    int tt = u >> 7;
                    int t = t0 + tt;
                    shd[u] = (t < TT) ? ((const float4*)&g_hb[p][t][0])[u & 127] : z;
                }
            }
            __syncthreads();

            // micro-tile: 4 rows x 8 t, f32x2 packed over k-pairs
            unsigned long long acc2[4][8];
#pragma unroll
            for (int j = 0; j < 4; j++)
#pragma unroll
                for (int i = 0; i < 8; i++) acc2[j][i] = 0ull;

            const float* wrow = sWb + (rg * 4) * HH;
            const float* hrow = sh + (tg * 8) * HH;
#pragma unroll 4
            for (int m = 0; m < 16; m++) {
                int ko = 32 * m + 2 * ks;
                unsigned long long w2[4], h2[8];
#pragma unroll
                for (int j = 0; j < 4; j++)
                    w2[j] = *(const unsigned long long*)(wrow + j * HH + ko);
#pragma unroll
                for (int i = 0; i < 8; i++)
                    h2[i] = *(const unsigned long long*)(hrow + i * HH + ko);
#pragma unroll
                for (int j = 0; j < 4; j++)
#pragma unroll
                    for (int i = 0; i < 8; i++)
                        acc2[j][i] = fma2_(w2[j], h2[i], acc2[j][i]);
            }

            // fold packed halves, reduce over 16-way k-split (lane bits 0..3)
#pragma unroll
            for (int j = 0; j < 4; j++)
#pragma unroll
                for (int i = 0; i < 8; i++) {
                    float v = unpack_sum_(acc2[j][i]);
                    v += __shfl_xor_sync(0xffffffffu, v, 1);
                    v += __shfl_xor_sync(0xffffffffu, v, 2);
                    v += __shfl_xor_sync(0xffffffffu, v, 4);
                    v += __shfl_xor_sync(0xffffffffu, v, 8);
                    if (ks == 0) sg[rg][tg * 8 + i][j] = v;
                }
            __syncthreads();

            // pointwise LSTM update for this tile (block's 4 hidden dims)
            int tcnt = TT - t0; if (tcnt > TTILE) tcnt = TTILE;
            for (int it = tid; it < 4 * tcnt; it += NT) {
                int tt = it >> 2, q = it & 3;
                int t = t0 + tt;
                int u = t - s;
                int jb = k0 + q;
                float gi = sg[0][tt][q] + g_gxb[u][jb];
                float gf = sg[1][tt][q] + g_gxb[u][HH + jb];
                float gg = sg[2][tt][q] + g_gxb[u][2 * HH + jb];
                float go = sg[3][tt][q] + g_gxb[u][3 * HH + jb];
                float c  = scb[t][q];
                float cn = sigmoidf_(gf) * c + sigmoidf_(gi) * tanhf(gg);
                float hn = sigmoidf_(go) * tanhf(cn);
                scb[t][q] = cn;
                g_hb[p2][t][jb] = hn;
                if (t == s) g_hb_final[t][jb] = hn;
            }
            __syncthreads();
        }

        // ======== grid barrier (volatile-poll release) ========
        if (tid == 0) {
            __threadfence();
            unsigned a = atomicAdd(&g_cnt, 1u);
            if (a == NB - 1) {
                atomicExch(&g_cnt, 0u);
                __threadfence();
                g_gen = (unsigned)(s + 1);
            } else {
                while (g_gen < (unsigned)(s + 1)) { }
            }
            __threadfence();
        }
        __syncthreads();
    }
}

// ---------------- final FC: logits = [hf|hb] @ fc_w^T + fc_b ----------------
// Tile 64 t x 128 v, 256 threads, micro 8t x 4v (v strided by 32),
// f32x2 packed over k-pairs. Rows stride 18 -> 2-phase-floor LDS.64.
#define FCT 64
#define FCV 128
#define FCK 16
#define FCP 18
__global__ void __launch_bounds__(256, 2)
fc_kernel(const float* __restrict__ fcw,
          const float* __restrict__ fcb,
          float* __restrict__ out) {
    __shared__ float As[FCT][FCP];
    __shared__ float Bs[FCV][FCP];
    int tid = threadIdx.x;  // 256
    int tg  = tid >> 5;     // 0..7 -> t rows tg*8..+8
    int vg  = tid & 31;     // v lanes, strided by 32
    int tbase = blockIdx.y * FCT;
    int vbase = blockIdx.x * FCV;

    unsigned long long acc2[8][4];
#pragma unroll
    for (int j = 0; j < 8; j++)
#pragma unroll
        for (int c = 0; c < 4; c++) acc2[j][c] = 0ull;

    for (int kc = 0; kc < KH2; kc += FCK) {
        // stage A: 64 x 16 (one float4 per thread)
        {
            int tt = tid >> 2, kq = tid & 3;
            int t = tbase + tt;
            int k = kc + 4 * kq;
            float4 a = make_float4(0.f, 0.f, 0.f, 0.f);
            if (t < TT)
                a = (k < HH) ? *(const float4*)&g_hf_all[t][k]
                             : *(const float4*)&g_hb_final[t][k - HH];
            *(float2*)&As[tt][4 * kq]     = make_float2(a.x, a.y);
            *(float2*)&As[tt][4 * kq + 2] = make_float2(a.z, a.w);
        }
        // stage B: 128 x 16 (two float4 per thread)
        for (int u = tid; u < 512; u += 256) {
            int vv = u >> 2, kq = u & 3;
            float4 b = *(const float4*)&fcw[(long)(vbase + vv) * KH2 + kc + 4 * kq];
            *(float2*)&Bs[vv][4 * kq]     = make_float2(b.x, b.y);
            *(float2*)&Bs[vv][4 * kq + 2] = make_float2(b.z, b.w);
        }
        __syncthreads();

#pragma unroll
        for (int k2 = 0; k2 < FCK / 2; k2++) {
            unsigned long long a2[8], b2[4];
#pragma unroll
            for (int j = 0; j < 8; j++)
                a2[j] = *(const unsigned long long*)&As[tg * 8 + j][2 * k2];
#pragma unroll
            for (int c = 0; c < 4; c++)
                b2[c] = *(const unsigned long long*)&Bs[vg + 32 * c][2 * k2];
#pragma unroll
            for (int j = 0; j < 8; j++)
#pragma unroll
                for (int c = 0; c < 4; c++)
                    acc2[j][c] = fma2_(a2[j], b2[c], acc2[j][c]);
        }
        __syncthreads();
    }

#pragma unroll
    for (int j = 0; j < 8; j++) {
        int t = tbase + tg * 8 + j;
        if (t >= TT) continue;
#pragma unroll
        for (int c = 0; c < 4; c++) {
            int v = vbase + vg + 32 * c;
            out[(long)t * VV + v] = unpack_sum_(acc2[j][c]) + fcb[v];
        }
    }
}

// ---------------- launch ----------------
extern "C" void kernel_launch(void* const* d_in, const int* in_sizes, int n_in,
                              void* d_out, int out_size) {
    const int*   x      = (const int*)d_in[0];
    const float* emb    = (const float*)d_in[1];
    const float* W_ih_f = (const float*)d_in[2];
    const float* W_hh_f = (const float*)d_in[3];
    const float* b_ih_f = (const float*)d_in[4];
    const float* b_hh_f = (const float*)d_in[5];
    const float* W_ih_b = (const float*)d_in[6];
    const float* W_hh_b = (const float*)d_in[7];
    const float* b_ih_b = (const float*)d_in[8];
    const float* b_hh_b = (const float*)d_in[9];
    const float* fc_w   = (const float*)d_in[10];
    const float* fc_b   = (const float*)d_in[11];
    float* out = (float*)d_out;

    const int dynBytes = (16 * HH + 16 * HH + TTILE * HH) * (int)sizeof(float);
    cudaFuncSetAttribute(scan_kernel,
                         cudaFuncAttributeMaxDynamicSharedMemorySize, dynBytes);

    init_kernel<<<64, 256>>>();
    input_gemm_kernel<<<256, 128>>>(x, emb, W_ih_f, b_ih_f, b_hh_f,
                                    W_ih_b, b_ih_b, b_hh_b);
    scan_kernel<<<NB, NT, dynBytes>>>(W_hh_f, W_hh_b);
    fc_kernel<<<dim3(VV / FCV, (TT + FCT - 1) / FCT), 256>>>(fc_w, fc_b, out);
}

// round 15
// speedup vs baseline: 2.6144x; 1.1749x over previous
#include <cuda_runtime.h>
#include <math.h>

// Problem constants
#define LQ 128     // sequence length
#define TT 127     // T = L-1 output rows
#define EE 256     // embedding dim
#define HH 512     // hidden
#define G4 2048    // 4*H gates
#define VV 32000   // vocab
#define KH2 1024   // 2*H

#define NB 128     // persistent scan blocks (one per SM, all co-resident)
#define NT 256     // threads per scan block
#define TTILE 64   // backward t rows per smem tile

// ---------------- device scratch (no allocs allowed) ----------------
__device__ float g_gxf[LQ][G4];        // emb @ W_ih_f^T + b_f
__device__ float g_gxb[LQ][G4];        // emb @ W_ih_b^T + b_b
__device__ float g_hf_all[TT][HH];     // forward hidden states
__device__ float g_hb_final[TT][HH];   // final backward hidden per row t
__device__ float g_hb[2][TT][HH];      // double-buffered backward h
__device__ float g_hfwd[2][HH];        // double-buffered forward h
__device__ unsigned g_cnt;             // grid barrier arrive counter
__device__ unsigned g_gen;             // grid barrier generation

__device__ __forceinline__ float sigmoidf_(float x) {
    return 1.f / (1.f + expf(-x));
}

__device__ __forceinline__ unsigned long long fma2_(unsigned long long a,
                                                    unsigned long long b,
                                                    unsigned long long c) {
    unsigned long long d;
    asm("fma.rn.f32x2 %0, %1, %2, %3;" : "=l"(d) : "l"(a), "l"(b), "l"(c));
    return d;
}

__device__ __forceinline__ float unpack_sum_(unsigned long long p) {
    float lo = __uint_as_float((unsigned)(p & 0xffffffffull));
    float hi = __uint_as_float((unsigned)(p >> 32));
    return lo + hi;
}

__device__ __forceinline__ void cp_async16_(void* smem, const void* gmem) {
    unsigned saddr = (unsigned)__cvta_generic_to_shared(smem);
    asm volatile("cp.async.cg.shared.global [%0], [%1], 16;\n"
                 :: "r"(saddr), "l"(gmem) : "memory");
}
#define CP_COMMIT() asm volatile("cp.async.commit_group;\n" ::: "memory")
#define CP_WAIT0()  asm volatile("cp.async.wait_group 0;\n" ::: "memory")

// ---------------- init: zero state + barrier vars ----------------
__global__ void init_kernel() {
    int idx = blockIdx.x * blockDim.x + threadIdx.x;
    int stride = gridDim.x * blockDim.x;
    float* hb0 = &g_hb[0][0][0];
    for (int i = idx; i < TT * HH; i += stride) hb0[i] = 0.f;
    if (idx < HH) g_hfwd[0][idx] = 0.f;
    if (idx == 0) { g_cnt = 0u; g_gen = 0u; }
}

// ---------------- gather + input GEMM (both directions) ----------------
__global__ void input_gemm_kernel(const int* __restrict__ x,
                                  const float* __restrict__ emb,
                                  const float* __restrict__ Wf,
                                  const float* __restrict__ bif,
                                  const float* __restrict__ bhf,
                                  const float* __restrict__ Wb,
                                  const float* __restrict__ bib,
                                  const float* __restrict__ bhb) {
    __shared__ float sW[16][EE];
    bool isB = (blockIdx.x >= 128);
    int j0 = (isB ? (blockIdx.x - 128) : blockIdx.x) * 16;
    const float* W  = isB ? Wb  : Wf;
    const float* bi = isB ? bib : bif;
    const float* bh = isB ? bhb : bhf;
    int tid = threadIdx.x;  // 128 threads

    for (int u = tid; u < 16 * EE; u += 128)
        sW[u >> 8][u & 255] = W[(j0 + (u >> 8)) * EE + (u & 255)];
    __syncthreads();

    int t = tid;
    int tok = x[t];
    const float* er = emb + (long)tok * EE;
    float acc[16];
#pragma unroll
    for (int r = 0; r < 16; r++) acc[r] = 0.f;

    for (int e = 0; e < EE; e += 4) {
        float4 e4 = *(const float4*)(er + e);
#pragma unroll
        for (int r = 0; r < 16; r++) {
            float4 w4 = *(const float4*)&sW[r][e];
            acc[r] += e4.x * w4.x + e4.y * w4.y + e4.z * w4.z + e4.w * w4.w;
        }
    }
    float* gx = isB ? &g_gxb[t][0] : &g_gxf[t][0];
#pragma unroll
    for (int r = 0; r < 16; r++) {
        int j = j0 + r;
        gx[j] = acc[r] + bi[j] + bh[j];
    }
}

// ---------------- persistent LSTM scan kernel ----------------
// 128 blocks, each owns hidden dims [4b, 4b+4) => 16 gate rows per direction.
// W slices in smem for the whole kernel. One grid barrier per step.
// Tile: 64 t rows x 16 gate rows x 512 k.
// Warp (rg = w&3 gate, kh = w>>2 k-half); lane (ks = l&3 k-split, tg = l>>2 t-group).
// Micro: 4 gate-rows x 8 t, fma.rn.f32x2 over k-pairs; 2-level shfl + smem
// partial combine across k-halves. Staged h uses per-row column rotation
// (+4*tg float2 cols) for conflict-free LDS.64.
extern __shared__ float dyn_smem[];

__global__ void __launch_bounds__(NT, 1)
scan_kernel(const float* __restrict__ Whf, const float* __restrict__ Whb) {
    float* sWb = dyn_smem;               // [16][HH]      32 KB
    float* sWf = sWb + 16 * HH;          // [16][HH]      32 KB
    float* sh  = sWf + 16 * HH;          // [TTILE][HH]  128 KB (swizzled cols)
    __shared__ float sgp[2][4][TTILE][4]; // k-half partials [kh][gate][tt][q]
    __shared__ float scb[TT][4];         // backward c, block's 4 dims
    __shared__ float shf[HH];            // forward h
    __shared__ float sgf[16];            // forward gate staging
    __shared__ float scf[4];             // forward c

    int tid = threadIdx.x;
    int k0 = blockIdx.x * 4;

    // load W slices once (row r = gate*4 + q -> global j = gate*HH + k0 + q)
    for (int u = tid; u < 16 * HH; u += NT) {
        int r = u >> 9, k = u & (HH - 1);
        int j = (r >> 2) * HH + k0 + (r & 3);
        sWb[r * HH + k] = Whb[(long)j * HH + k];
        sWf[r * HH + k] = Whf[(long)j * HH + k];
    }
    for (int u = tid; u < TT; u += NT) {
        scb[u][0] = 0.f; scb[u][1] = 0.f; scb[u][2] = 0.f; scb[u][3] = 0.f;
    }
    if (tid < 4) scf[tid] = 0.f;
    __syncthreads();

    int lane = tid & 31;
    int warp = tid >> 5;     // 8 warps
    int rg   = warp & 3;     // gate (rows rg*4 .. rg*4+3)
    int kh   = warp >> 2;    // k-half 0/1
    int ks   = lane & 3;     // 4-way k-split within half
    int tg   = lane >> 2;    // 0..7 -> t rows tg*8 .. tg*8+7

    for (int s = 0; s < TT; s++) {
        int p = s & 1, p2 = p ^ 1;

        // ---- issue async stage of first backward tile (overlaps forward) ----
        {
            int t0 = s;
            int tcnt = TT - t0; if (tcnt > TTILE) tcnt = TTILE;
            for (int u = tid; u < tcnt * 128; u += NT) {
                int row = u >> 7, q = u & 127;
                int c0 = (2 * q + 4 * ((row >> 3) & 7)) & 255;
                cp_async16_(sh + row * HH + 2 * c0, &g_hb[p][t0 + row][4 * q]);
            }
            CP_COMMIT();
        }

        // ======== forward chain (16 rows) ========
        for (int u = tid; u < HH; u += NT) shf[u] = g_hfwd[p][u];
        __syncthreads();
        {
            int r0 = 2 * warp;   // warp handles rows r0, r0+1
            float a0 = 0.f, a1 = 0.f;
            const float* w0 = sWf + r0 * HH;
            const float* w1 = w0 + HH;
#pragma unroll
            for (int m = 0; m < 16; m++) {
                float h = shf[lane + 32 * m];
                a0 += w0[lane + 32 * m] * h;
                a1 += w1[lane + 32 * m] * h;
            }
#pragma unroll
            for (int off = 16; off >= 1; off >>= 1) {
                a0 += __shfl_xor_sync(0xffffffffu, a0, off);
                a1 += __shfl_xor_sync(0xffffffffu, a1, off);
            }
            if (lane == 0) { sgf[r0] = a0; sgf[r0 + 1] = a1; }
        }
        __syncthreads();
        if (tid < 4) {
            int q = tid, jb = k0 + q;
            float gi = sgf[0 * 4 + q] + g_gxf[s][jb];
            float gf = sgf[1 * 4 + q] + g_gxf[s][HH + jb];
            float gg = sgf[2 * 4 + q] + g_gxf[s][2 * HH + jb];
            float go = sgf[3 * 4 + q] + g_gxf[s][3 * HH + jb];
            float c  = scf[q];
            float cn = sigmoidf_(gf) * c + sigmoidf_(gi) * tanhf(gg);
            float hn = sigmoidf_(go) * tanhf(cn);
            scf[q] = cn;
            g_hfwd[p2][jb]  = hn;
            g_hf_all[s][jb] = hn;
        }

        // ---- wait for first tile stage ----
        CP_WAIT0();
        __syncthreads();

        // ======== backward prefix LSTMs: rows t in [s, 126] ========
        for (int t0 = s; t0 < TT; t0 += TTILE) {
            int tcnt = TT - t0; if (tcnt > TTILE) tcnt = TTILE;
            int rmax = tcnt - tg * 8;   // valid i range for this lane's t-group

            // micro-tile: 4 gate-rows x 8 t, f32x2 over k-pairs
            unsigned long long acc2[4][8];
#pragma unroll
            for (int j = 0; j < 4; j++)
#pragma unroll
                for (int i = 0; i < 8; i++) acc2[j][i] = 0ull;

            const float* wrow = sWb + (rg * 4) * HH;
            const float* hrow = sh + (tg * 8) * HH;
#pragma unroll 4
            for (int m = 0; m < 32; m++) {
                int kp = kh * 128 + 4 * m + ks;            // logical float2 col
                int kc = 2 * ((kp + 4 * tg) & 255);        // swizzled float idx
                unsigned long long w2[4], h2[8];
#pragma unroll
                for (int j = 0; j < 4; j++)
                    w2[j] = *(const unsigned long long*)(wrow + j * HH + 2 * kp);
#pragma unroll
                for (int i = 0; i < 8; i++)
                    if (i < rmax)
                        h2[i] = *(const unsigned long long*)(hrow + i * HH + kc);
#pragma unroll
                for (int j = 0; j < 4; j++)
#pragma unroll
                    for (int i = 0; i < 8; i++)
                        acc2[j][i] = fma2_(w2[j], h2[i], acc2[j][i]);
            }

            // fold halves, 2-level shfl over ks (lane bits 0..1), store partials
#pragma unroll
            for (int i = 0; i < 8; i++) {
                float v[4];
#pragma unroll
                for (int j = 0; j < 4; j++) {
                    float a = unpack_sum_(acc2[j][i]);
                    a += __shfl_xor_sync(0xffffffffu, a, 1);
                    a += __shfl_xor_sync(0xffffffffu, a, 2);
                    v[j] = a;
                }
                if (ks == 0 && i < rmax)
                    *(float4*)&sgp[kh][rg][tg * 8 + i][0] =
                        make_float4(v[0], v[1], v[2], v[3]);
            }
            __syncthreads();

            // issue next tile's stage (overlaps pointwise update)
            int tn = t0 + TTILE;
            if (tn < TT) {
                int tc2 = TT - tn; if (tc2 > TTILE) tc2 = TTILE;
                for (int u = tid; u < tc2 * 128; u += NT) {
                    int row = u >> 7, q = u & 127;
                    int c0 = (2 * q + 4 * ((row >> 3) & 7)) & 255;
                    cp_async16_(sh + row * HH + 2 * c0, &g_hb[p][tn + row][4 * q]);
                }
                CP_COMMIT();
            }

            // pointwise LSTM update (block's 4 hidden dims)
            if (tid < 4 * tcnt) {
                int tt = tid >> 2, q = tid & 3;
                int t = t0 + tt;
                int u = t - s;
                int jb = k0 + q;
                float gi = sgp[0][0][tt][q] + sgp[1][0][tt][q] + g_gxb[u][jb];
                float gf = sgp[0][1][tt][q] + sgp[1][1][tt][q] + g_gxb[u][HH + jb];
                float gg = sgp[0][2][tt][q] + sgp[1][2][tt][q] + g_gxb[u][2 * HH + jb];
                float go = sgp[0][3][tt][q] + sgp[1][3][tt][q] + g_gxb[u][3 * HH + jb];
                float c  = scb[t][q];
                float cn = sigmoidf_(gf) * c + sigmoidf_(gi) * tanhf(gg);
                float hn = sigmoidf_(go) * tanhf(cn);
                scb[t][q] = cn;
                g_hb[p2][t][jb] = hn;
                if (t == s) g_hb_final[t][jb] = hn;
            }
            if (tn < TT) CP_WAIT0();
            __syncthreads();
        }

        // ======== grid barrier (acq_rel arrive, release/acquire hand-off) ====
        if (tid == 0) {
            unsigned a;
            asm volatile("fence.acq_rel.gpu;" ::: "memory");
            asm volatile("atom.acq_rel.gpu.add.u32 %0, [%1], %2;"
                         : "=r"(a) : "l"(&g_cnt), "r"(1u) : "memory");
            if (a == NB - 1) {
                asm volatile("st.relaxed.gpu.u32 [%0], %1;"
                             :: "l"(&g_cnt), "r"(0u) : "memory");
                asm volatile("st.release.gpu.u32 [%0], %1;"
                             :: "l"(&g_gen), "r"((unsigned)(s + 1)) : "memory");
            } else {
                unsigned g;
                do {
                    asm volatile("ld.acquire.gpu.u32 %0, [%1];"
                                 : "=r"(g) : "l"(&g_gen) : "memory");
                } while (g < (unsigned)(s + 1));
            }
        }
        __syncthreads();
    }
}

// ---------------- final FC: logits = [hf|hb] @ fc_w^T + fc_b ----------------
// Tile 64 t x 128 v, 256 threads, micro 8t x 4v (v strided by 32),
// f32x2 packed over k-pairs. Rows stride 18 -> 2-phase-floor LDS.64.
#define FCT 64
#define FCV 128
#define FCK 16
#define FCP 18
__global__ void __launch_bounds__(256, 2)
fc_kernel(const float* __restrict__ fcw,
          const float* __restrict__ fcb,
          float* __restrict__ out) {
    __shared__ float As[FCT][FCP];
    __shared__ float Bs[FCV][FCP];
    int tid = threadIdx.x;  // 256
    int tg  = tid >> 5;     // 0..7 -> t rows tg*8..+8
    int vg  = tid & 31;     // v lanes, strided by 32
    int tbase = blockIdx.y * FCT;
    int vbase = blockIdx.x * FCV;

    unsigned long long acc2[8][4];
#pragma unroll
    for (int j = 0; j < 8; j++)
#pragma unroll
        for (int c = 0; c < 4; c++) acc2[j][c] = 0ull;

    for (int kc = 0; kc < KH2; kc += FCK) {
        // stage A: 64 x 16 (one float4 per thread)
        {
            int tt = tid >> 2, kq = tid & 3;
            int t = tbase + tt;
            int k = kc + 4 * kq;
            float4 a = make_float4(0.f, 0.f, 0.f, 0.f);
            if (t < TT)
                a = (k < HH) ? *(const float4*)&g_hf_all[t][k]
                             : *(const float4*)&g_hb_final[t][k - HH];
            *(float2*)&As[tt][4 * kq]     = make_float2(a.x, a.y);
            *(float2*)&As[tt][4 * kq + 2] = make_float2(a.z, a.w);
        }
        // stage B: 128 x 16 (two float4 per thread)
        for (int u = tid; u < 512; u += 256) {
            int vv = u >> 2, kq = u & 3;
            float4 b = *(const float4*)&fcw[(long)(vbase + vv) * KH2 + kc + 4 * kq];
            *(float2*)&Bs[vv][4 * kq]     = make_float2(b.x, b.y);
            *(float2*)&Bs[vv][4 * kq + 2] = make_float2(b.z, b.w);
        }
        __syncthreads();

#pragma unroll
        for (int k2 = 0; k2 < FCK / 2; k2++) {
            unsigned long long a2[8], b2[4];
#pragma unroll
            for (int j = 0; j < 8; j++)
                a2[j] = *(const unsigned long long*)&As[tg * 8 + j][2 * k2];
#pragma unroll
            for (int c = 0; c < 4; c++)
                b2[c] = *(const unsigned long long*)&Bs[vg + 32 * c][2 * k2];
#pragma unroll
            for (int j = 0; j < 8; j++)
#pragma unroll
                for (int c = 0; c < 4; c++)
                    acc2[j][c] = fma2_(a2[j], b2[c], acc2[j][c]);
        }
        __syncthreads();
    }

#pragma unroll
    for (int j = 0; j < 8; j++) {
        int t = tbase + tg * 8 + j;
        if (t >= TT) continue;
#pragma unroll
        for (int c = 0; c < 4; c++) {
            int v = vbase + vg + 32 * c;
            out[(long)t * VV + v] = unpack_sum_(acc2[j][c]) + fcb[v];
        }
    }
}

// ---------------- launch ----------------
extern "C" void kernel_launch(void* const* d_in, const int* in_sizes, int n_in,
                              void* d_out, int out_size) {
    const int*   x      = (const int*)d_in[0];
    const float* emb    = (const float*)d_in[1];
    const float* W_ih_f = (const float*)d_in[2];
    const float* W_hh_f = (const float*)d_in[3];
    const float* b_ih_f = (const float*)d_in[4];
    const float* b_hh_f = (const float*)d_in[5];
    const float* W_ih_b = (const float*)d_in[6];
    const float* W_hh_b = (const float*)d_in[7];
    const float* b_ih_b = (const float*)d_in[8];
    const float* b_hh_b = (const float*)d_in[9];
    const float* fc_w   = (const float*)d_in[10];
    const float* fc_b   = (const float*)d_in[11];
    float* out = (float*)d_out;

    const int dynBytes = (16 * HH + 16 * HH + TTILE * HH) * (int)sizeof(float);
    cudaFuncSetAttribute(scan_kernel,
                         cudaFuncAttributeMaxDynamicSharedMemorySize, dynBytes);

    init_kernel<<<64, 256>>>();
    input_gemm_kernel<<<256, 128>>>(x, emb, W_ih_f, b_ih_f, b_hh_f,
                                    W_ih_b, b_ih_b, b_hh_b);
    scan_kernel<<<NB, NT, dynBytes>>>(W_hh_f, W_hh_b);
    fc_kernel<<<dim3(VV / FCV, (TT + FCT - 1) / FCT), 256>>>(fc_w, fc_b, out);
}